// round 10
// baseline (speedup 1.0000x reference)
#include <cuda_runtime.h>
#include <cuda_fp16.h>

#define N_USERS  100000
#define N_ITEMS  50000
#define N_TOTAL  150000
#define DIM      64
#define NNZ      1200000
#define BATCH    4096
#define SCAN_B   1024
#define NBLK_SCAN ((N_TOTAL + SCAN_B - 1) / SCAN_B)   // 147

// ---- scratch (device globals; no allocation allowed) ----
__device__ int      g_count[N_TOTAL];
__device__ int      g_rowptr[N_TOTAL];       // block-LOCAL prefix; scatter turns it into local incl
__device__ int      g_bsum[NBLK_SCAN];       // exclusive block offsets (added on the fly)
__device__ unsigned g_scan_done;             // zero-init; reset by last block
__device__ int2     g_csr[NNZ];              // {col, val bits} interleaved
__device__ __half2  g_E0h[N_TOTAL * 32];     // half2 = (dim lane, dim lane+32)
__device__ __half2  g_E1h[N_TOTAL * 32];
__device__ __half2  g_E2h[N_TOTAL * 32];

// ---------------- prep: E0 -> fp16 table, and zero the histogram ----------------

__global__ void __launch_bounds__(256) k_prep(const float* __restrict__ E0) {
    int t    = blockIdx.x * blockDim.x + threadIdx.x;
    int w    = t >> 5;
    int lane = t & 31;
    if (w >= N_TOTAL) return;
    float a = E0[(size_t)w * DIM + lane];
    float b = E0[(size_t)w * DIM + lane + 32];
    g_E0h[(size_t)w * 32 + lane] = __floats2half2_rn(a, b);
    if (lane == 0) g_count[w] = 0;
}

// ---------------- CSR build ----------------

// 4 edges per thread — 4 independent atomics in flight
__global__ void k_hist(const int4* __restrict__ row4) {
    int t = blockIdx.x * blockDim.x + threadIdx.x;
    if (t < NNZ / 4) {
        int4 r = row4[t];
        atomicAdd(&g_count[r.x], 1);
        atomicAdd(&g_count[r.y], 1);
        atomicAdd(&g_count[r.z], 1);
        atomicAdd(&g_count[r.w], 1);
    }
}

// per-block exclusive scan (shfl-based); last block also scans the block sums.
// g_rowptr keeps only the BLOCK-LOCAL exclusive prefix; g_bsum holds the global
// block offsets, added on the fly by scatter / row_range (saves the scan3 pass).
__global__ void __launch_bounds__(SCAN_B) k_scan1() {
    __shared__ int  wsum[32];
    __shared__ bool is_last;
    int tid  = threadIdx.x;
    int lane = tid & 31, wid = tid >> 5;
    int i = blockIdx.x * SCAN_B + tid;
    int v = (i < N_TOTAL) ? g_count[i] : 0;

    int x = v;
    #pragma unroll
    for (int off = 1; off < 32; off <<= 1) {
        int t = __shfl_up_sync(0xffffffffu, x, off);
        if (lane >= off) x += t;
    }
    if (lane == 31) wsum[wid] = x;
    __syncthreads();
    if (wid == 0) {
        int s = wsum[lane];
        #pragma unroll
        for (int off = 1; off < 32; off <<= 1) {
            int t = __shfl_up_sync(0xffffffffu, s, off);
            if (lane >= off) s += t;
        }
        wsum[lane] = s;
    }
    __syncthreads();
    int incl = x + (wid ? wsum[wid - 1] : 0);
    if (i < N_TOTAL) g_rowptr[i] = incl - v;          // block-local exclusive
    if (tid == SCAN_B - 1) g_bsum[blockIdx.x] = incl;

    // fold the block-sum scan into the last block to finish
    __threadfence();
    if (tid == 0)
        is_last = (atomicAdd(&g_scan_done, 1u) == (unsigned)(gridDim.x - 1));
    __syncthreads();
    if (is_last && tid < 32) {
        int carry = 0;
        for (int base = 0; base < NBLK_SCAN; base += 32) {
            int bi = base + lane;
            int bv = (bi < NBLK_SCAN) ? g_bsum[bi] : 0;
            int y = bv;
            #pragma unroll
            for (int off = 1; off < 32; off <<= 1) {
                int t = __shfl_up_sync(0xffffffffu, y, off);
                if (lane >= off) y += t;
            }
            if (bi < NBLK_SCAN) g_bsum[bi] = y - bv + carry;   // exclusive + carry
            carry += __shfl_sync(0xffffffffu, y, 31);
        }
        if (lane == 0) g_scan_done = 0u;                       // reset for next replay
    }
}

// 4 edges per thread; atomic on block-local prefix (uniqueness preserved),
// global slot = local slot + bsum[row block]. rowptr[r] ends as local inclusive.
__global__ void k_scatter(const int4* __restrict__ row4,
                          const int4* __restrict__ col4,
                          const float4* __restrict__ val4) {
    int t = blockIdx.x * blockDim.x + threadIdx.x;
    if (t < NNZ / 4) {
        int4   r = row4[t];
        int4   c = col4[t];
        float4 v = val4[t];
        int p0 = atomicAdd(&g_rowptr[r.x], 1) + g_bsum[r.x >> 10];
        int p1 = atomicAdd(&g_rowptr[r.y], 1) + g_bsum[r.y >> 10];
        int p2 = atomicAdd(&g_rowptr[r.z], 1) + g_bsum[r.z >> 10];
        int p3 = atomicAdd(&g_rowptr[r.w], 1) + g_bsum[r.w >> 10];
        g_csr[p0] = make_int2(c.x, __float_as_int(v.x));
        g_csr[p1] = make_int2(c.y, __float_as_int(v.y));
        g_csr[p2] = make_int2(c.z, __float_as_int(v.z));
        g_csr[p3] = make_int2(c.w, __float_as_int(v.w));
    }
}

// ---------------- SpMM helpers ----------------
// post-scatter: global end(r) = rowptr[r] + bsum[r>>10]   (rowptr[r] = local incl)
//               global start(r) = r==0 ? 0 : end(r-1)

__device__ __forceinline__ void row_range(int r, int& s, int& e) {
    e = g_rowptr[r] + g_bsum[r >> 10];
    s = (r == 0) ? 0 : (g_rowptr[r - 1] + g_bsum[(r - 1) >> 10]);
}

// gather from fp16 table: one LDG.32 per neighbor (128B/warp), fp32 accumulate
__device__ __forceinline__ void row_gemv_h(const __half2* __restrict__ Eh, int r, int lane,
                                           float& a0, float& a1) {
    int s, e; row_range(r, s, e);
    a0 = 0.f; a1 = 0.f;
    int j = s;
    for (; j + 2 <= e; j += 2) {
        int2 cv0 = g_csr[j];
        int2 cv1 = g_csr[j + 1];
        float2 x0 = __half22float2(Eh[(size_t)cv0.x * 32 + lane]);
        float2 x1 = __half22float2(Eh[(size_t)cv1.x * 32 + lane]);
        float v0 = __int_as_float(cv0.y), v1 = __int_as_float(cv1.y);
        a0 = fmaf(v0, x0.x, a0); a1 = fmaf(v0, x0.y, a1);
        a0 = fmaf(v1, x1.x, a0); a1 = fmaf(v1, x1.y, a1);
    }
    if (j < e) {
        int2 cv = g_csr[j];
        float2 x0 = __half22float2(Eh[(size_t)cv.x * 32 + lane]);
        float v0 = __int_as_float(cv.y);
        a0 = fmaf(v0, x0.x, a0);
        a1 = fmaf(v0, x0.y, a1);
    }
}

__global__ void __launch_bounds__(256) k_spmm1() {
    int w    = (blockIdx.x * blockDim.x + threadIdx.x) >> 5;
    int lane = threadIdx.x & 31;
    if (w >= N_TOTAL) return;
    float a0, a1;
    row_gemv_h(g_E0h, w, lane, a0, a1);
    g_E1h[(size_t)w * 32 + lane] = __float22half2_rn(make_float2(a0, a1));
}

__global__ void __launch_bounds__(256) k_spmm2() {
    int w    = (blockIdx.x * blockDim.x + threadIdx.x) >> 5;
    int lane = threadIdx.x & 31;
    if (w >= N_TOTAL) return;
    float a0, a1;
    row_gemv_h(g_E1h, w, lane, a0, a1);
    g_E2h[(size_t)w * 32 + lane] = __float22half2_rn(make_float2(a0, a1));
}

// ---------------- fused layer-3 + average + gather ----------------
// out slots: 0 u_emb, 1 pos_emb, 2 neg_emb, 3 u_emb0, 4 pos_emb0, 5 neg_emb0
// *_emb0 slots read fp32 E0 directly — exact.
__global__ void __launch_bounds__(256) k_gather(const int* __restrict__ users,
                                                const int* __restrict__ pos,
                                                const int* __restrict__ neg,
                                                const float* __restrict__ E0,
                                                float* __restrict__ out) {
    int w    = (blockIdx.x * blockDim.x + threadIdx.x) >> 5;
    int lane = threadIdx.x & 31;
    if (w >= 3 * BATCH) return;
    int slot = w / BATCH;
    int b    = w - slot * BATCH;
    int r;
    if (slot == 0)      r = users[b];
    else if (slot == 1) r = N_USERS + pos[b];
    else                r = N_USERS + neg[b];

    // E3 row = (A @ E2)[r] — only needed at gathered rows
    float a0, a1;
    row_gemv_h(g_E2h, r, lane, a0, a1);

    size_t ro = (size_t)r * DIM;
    float  e0a = E0[ro + lane], e0b = E0[ro + lane + 32];
    float2 e1  = __half22float2(g_E1h[(size_t)r * 32 + lane]);
    float2 e2  = __half22float2(g_E2h[(size_t)r * 32 + lane]);
    float f0 = (e0a + e1.x + e2.x + a0) * 0.25f;
    float f1 = (e0b + e1.y + e2.y + a1) * 0.25f;

    size_t base  = (size_t)slot * BATCH * DIM + (size_t)b * DIM;
    size_t base0 = (size_t)(slot + 3) * BATCH * DIM + (size_t)b * DIM;
    out[base  + lane]      = f0;
    out[base  + lane + 32] = f1;
    out[base0 + lane]      = e0a;
    out[base0 + lane + 32] = e0b;
}

// ---------------- launch ----------------

extern "C" void kernel_launch(void* const* d_in, const int* in_sizes, int n_in,
                              void* d_out, int out_size) {
    const int*   users = (const int*)  d_in[0];
    const int*   pos   = (const int*)  d_in[1];
    const int*   neg   = (const int*)  d_in[2];
    const float* E0    = (const float*)d_in[3];
    const int*   arow  = (const int*)  d_in[4];
    const int*   acol  = (const int*)  d_in[5];
    const float* avals = (const float*)d_in[6];
    float* out = (float*)d_out;

    const int e4_blocks = (NNZ / 4 + 255) / 256;          // 1172
    const int prep_blocks = (N_TOTAL * 32 + 255) / 256;   // 18750

    k_prep<<<prep_blocks, 256>>>(E0);                      // E0->fp16 + zero counts
    k_hist<<<e4_blocks, 256>>>((const int4*)arow);
    k_scan1<<<NBLK_SCAN, SCAN_B>>>();                      // + fused block-sum scan
    k_scatter<<<e4_blocks, 256>>>((const int4*)arow, (const int4*)acol, (const float4*)avals);

    k_spmm1<<<prep_blocks, 256>>>();                       // 1 warp per row
    k_spmm2<<<prep_blocks, 256>>>();

    const int gat_blocks = (3 * BATCH * 32 + 255) / 256;
    k_gather<<<gat_blocks, 256>>>(users, pos, neg, E0, out);
}

// round 13
// speedup vs baseline: 1.0939x; 1.0939x over previous
#include <cuda_runtime.h>
#include <cuda_fp16.h>

#define N_USERS  100000
#define N_ITEMS  50000
#define N_TOTAL  150000
#define DIM      64
#define NNZ      1200000
#define BATCH    4096
#define SCAN_B   1024
#define NBLK_SCAN ((N_TOTAL + SCAN_B - 1) / SCAN_B)   // 147

// ---- scratch (device globals; no allocation allowed) ----
__device__ int      g_count[N_TOTAL];
__device__ int      g_rowptr[N_TOTAL];       // block-LOCAL prefix; scatter turns it into local incl
__device__ int      g_bsum[NBLK_SCAN];       // exclusive block offsets (added on the fly)
__device__ unsigned g_scan_done;             // zero-init; reset by last block
__device__ int2     g_csr[NNZ];              // {col, val bits} interleaved
__device__ __half2  g_E1h[N_TOTAL * 32];     // half2 = (dim lane, dim lane+32)
__device__ __half2  g_E2h[N_TOTAL * 32];

// ---------------- CSR build ----------------

__global__ void k_zero() {
    int i = blockIdx.x * blockDim.x + threadIdx.x;
    if (i < N_TOTAL) g_count[i] = 0;
}

// 8 edges per thread — 8 independent atomics in flight (latency-bound fix)
__global__ void k_hist(const int4* __restrict__ row4) {
    int t = blockIdx.x * blockDim.x + threadIdx.x;
    if (t < NNZ / 8) {
        int4 ra = row4[2 * t];
        int4 rb = row4[2 * t + 1];
        atomicAdd(&g_count[ra.x], 1);
        atomicAdd(&g_count[ra.y], 1);
        atomicAdd(&g_count[ra.z], 1);
        atomicAdd(&g_count[ra.w], 1);
        atomicAdd(&g_count[rb.x], 1);
        atomicAdd(&g_count[rb.y], 1);
        atomicAdd(&g_count[rb.z], 1);
        atomicAdd(&g_count[rb.w], 1);
    }
}

// per-block exclusive scan (shfl-based); last block also scans the block sums.
// g_rowptr keeps only the BLOCK-LOCAL exclusive prefix; g_bsum holds the global
// block offsets, added on the fly by scatter / row_range (saves the scan3 pass).
__global__ void __launch_bounds__(SCAN_B) k_scan1() {
    __shared__ int  wsum[32];
    __shared__ bool is_last;
    int tid  = threadIdx.x;
    int lane = tid & 31, wid = tid >> 5;
    int i = blockIdx.x * SCAN_B + tid;
    int v = (i < N_TOTAL) ? g_count[i] : 0;

    int x = v;
    #pragma unroll
    for (int off = 1; off < 32; off <<= 1) {
        int t = __shfl_up_sync(0xffffffffu, x, off);
        if (lane >= off) x += t;
    }
    if (lane == 31) wsum[wid] = x;
    __syncthreads();
    if (wid == 0) {
        int s = wsum[lane];
        #pragma unroll
        for (int off = 1; off < 32; off <<= 1) {
            int t = __shfl_up_sync(0xffffffffu, s, off);
            if (lane >= off) s += t;
        }
        wsum[lane] = s;
    }
    __syncthreads();
    int incl = x + (wid ? wsum[wid - 1] : 0);
    if (i < N_TOTAL) g_rowptr[i] = incl - v;          // block-local exclusive
    if (tid == SCAN_B - 1) g_bsum[blockIdx.x] = incl;

    // fold the block-sum scan into the last block to finish
    __threadfence();
    if (tid == 0)
        is_last = (atomicAdd(&g_scan_done, 1u) == (unsigned)(gridDim.x - 1));
    __syncthreads();
    if (is_last && tid < 32) {
        int carry = 0;
        for (int base = 0; base < NBLK_SCAN; base += 32) {
            int bi = base + lane;
            int bv = (bi < NBLK_SCAN) ? g_bsum[bi] : 0;
            int y = bv;
            #pragma unroll
            for (int off = 1; off < 32; off <<= 1) {
                int t = __shfl_up_sync(0xffffffffu, y, off);
                if (lane >= off) y += t;
            }
            if (bi < NBLK_SCAN) g_bsum[bi] = y - bv + carry;   // exclusive + carry
            carry += __shfl_sync(0xffffffffu, y, 31);
        }
        if (lane == 0) g_scan_done = 0u;                       // reset for next replay
    }
}

// 8 edges per thread; atomic on block-local prefix (uniqueness preserved),
// global slot = local slot + bsum[row block]. rowptr[r] ends as local inclusive.
__global__ void k_scatter(const int4* __restrict__ row4,
                          const int4* __restrict__ col4,
                          const float4* __restrict__ val4) {
    int t = blockIdx.x * blockDim.x + threadIdx.x;
    if (t < NNZ / 8) {
        int4   ra = row4[2 * t],     rb = row4[2 * t + 1];
        int4   ca = col4[2 * t],     cb = col4[2 * t + 1];
        float4 va = val4[2 * t],     vb = val4[2 * t + 1];
        int p0 = atomicAdd(&g_rowptr[ra.x], 1) + g_bsum[ra.x >> 10];
        int p1 = atomicAdd(&g_rowptr[ra.y], 1) + g_bsum[ra.y >> 10];
        int p2 = atomicAdd(&g_rowptr[ra.z], 1) + g_bsum[ra.z >> 10];
        int p3 = atomicAdd(&g_rowptr[ra.w], 1) + g_bsum[ra.w >> 10];
        int p4 = atomicAdd(&g_rowptr[rb.x], 1) + g_bsum[rb.x >> 10];
        int p5 = atomicAdd(&g_rowptr[rb.y], 1) + g_bsum[rb.y >> 10];
        int p6 = atomicAdd(&g_rowptr[rb.z], 1) + g_bsum[rb.z >> 10];
        int p7 = atomicAdd(&g_rowptr[rb.w], 1) + g_bsum[rb.w >> 10];
        g_csr[p0] = make_int2(ca.x, __float_as_int(va.x));
        g_csr[p1] = make_int2(ca.y, __float_as_int(va.y));
        g_csr[p2] = make_int2(ca.z, __float_as_int(va.z));
        g_csr[p3] = make_int2(ca.w, __float_as_int(va.w));
        g_csr[p4] = make_int2(cb.x, __float_as_int(vb.x));
        g_csr[p5] = make_int2(cb.y, __float_as_int(vb.y));
        g_csr[p6] = make_int2(cb.z, __float_as_int(vb.z));
        g_csr[p7] = make_int2(cb.w, __float_as_int(vb.w));
    }
}

// ---------------- SpMM helpers ----------------
// post-scatter: global end(r) = rowptr[r] + bsum[r>>10]   (rowptr[r] = local incl)
//               global start(r) = r==0 ? 0 : end(r-1)

__device__ __forceinline__ void row_range(int r, int& s, int& e) {
    e = g_rowptr[r] + g_bsum[r >> 10];
    s = (r == 0) ? 0 : (g_rowptr[r - 1] + g_bsum[(r - 1) >> 10]);
}

// gather from fp32 table: 4-neighbor unroll -> 8 independent LDG.32 in flight
__device__ __forceinline__ void row_gemv_f(const float* __restrict__ E, int r, int lane,
                                           float& a0, float& a1) {
    int s, e; row_range(r, s, e);
    a0 = 0.f; a1 = 0.f;
    int j = s;
    for (; j + 4 <= e; j += 4) {
        int2 cv0 = g_csr[j];
        int2 cv1 = g_csr[j + 1];
        int2 cv2 = g_csr[j + 2];
        int2 cv3 = g_csr[j + 3];
        const float* __restrict__ e0 = E + (size_t)cv0.x * DIM;
        const float* __restrict__ e1 = E + (size_t)cv1.x * DIM;
        const float* __restrict__ e2 = E + (size_t)cv2.x * DIM;
        const float* __restrict__ e3 = E + (size_t)cv3.x * DIM;
        float x00 = e0[lane], x01 = e0[lane + 32];
        float x10 = e1[lane], x11 = e1[lane + 32];
        float x20 = e2[lane], x21 = e2[lane + 32];
        float x30 = e3[lane], x31 = e3[lane + 32];
        float v0 = __int_as_float(cv0.y), v1 = __int_as_float(cv1.y);
        float v2 = __int_as_float(cv2.y), v3 = __int_as_float(cv3.y);
        a0 = fmaf(v0, x00, a0); a1 = fmaf(v0, x01, a1);
        a0 = fmaf(v1, x10, a0); a1 = fmaf(v1, x11, a1);
        a0 = fmaf(v2, x20, a0); a1 = fmaf(v2, x21, a1);
        a0 = fmaf(v3, x30, a0); a1 = fmaf(v3, x31, a1);
    }
    for (; j < e; j++) {
        int2 cv = g_csr[j];
        const float* __restrict__ e0 = E + (size_t)cv.x * DIM;
        float v0 = __int_as_float(cv.y);
        a0 = fmaf(v0, e0[lane],      a0);
        a1 = fmaf(v0, e0[lane + 32], a1);
    }
}

// gather from fp16 table: 4-neighbor unroll -> 4 independent LDG.32 in flight
__device__ __forceinline__ void row_gemv_h(const __half2* __restrict__ Eh, int r, int lane,
                                           float& a0, float& a1) {
    int s, e; row_range(r, s, e);
    a0 = 0.f; a1 = 0.f;
    int j = s;
    for (; j + 4 <= e; j += 4) {
        int2 cv0 = g_csr[j];
        int2 cv1 = g_csr[j + 1];
        int2 cv2 = g_csr[j + 2];
        int2 cv3 = g_csr[j + 3];
        float2 x0 = __half22float2(Eh[(size_t)cv0.x * 32 + lane]);
        float2 x1 = __half22float2(Eh[(size_t)cv1.x * 32 + lane]);
        float2 x2 = __half22float2(Eh[(size_t)cv2.x * 32 + lane]);
        float2 x3 = __half22float2(Eh[(size_t)cv3.x * 32 + lane]);
        float v0 = __int_as_float(cv0.y), v1 = __int_as_float(cv1.y);
        float v2 = __int_as_float(cv2.y), v3 = __int_as_float(cv3.y);
        a0 = fmaf(v0, x0.x, a0); a1 = fmaf(v0, x0.y, a1);
        a0 = fmaf(v1, x1.x, a0); a1 = fmaf(v1, x1.y, a1);
        a0 = fmaf(v2, x2.x, a0); a1 = fmaf(v2, x2.y, a1);
        a0 = fmaf(v3, x3.x, a0); a1 = fmaf(v3, x3.y, a1);
    }
    for (; j < e; j++) {
        int2 cv = g_csr[j];
        float2 x0 = __half22float2(Eh[(size_t)cv.x * 32 + lane]);
        float v0 = __int_as_float(cv.y);
        a0 = fmaf(v0, x0.x, a0);
        a1 = fmaf(v0, x0.y, a1);
    }
}

__global__ void __launch_bounds__(256) k_spmm1(const float* __restrict__ E0) {
    int w    = (blockIdx.x * blockDim.x + threadIdx.x) >> 5;
    int lane = threadIdx.x & 31;
    if (w >= N_TOTAL) return;
    float a0, a1;
    row_gemv_f(E0, w, lane, a0, a1);
    g_E1h[(size_t)w * 32 + lane] = __float22half2_rn(make_float2(a0, a1));
}

__global__ void __launch_bounds__(256) k_spmm2() {
    int w    = (blockIdx.x * blockDim.x + threadIdx.x) >> 5;
    int lane = threadIdx.x & 31;
    if (w >= N_TOTAL) return;
    float a0, a1;
    row_gemv_h(g_E1h, w, lane, a0, a1);
    g_E2h[(size_t)w * 32 + lane] = __float22half2_rn(make_float2(a0, a1));
}

// ---------------- fused layer-3 + average + gather ----------------
// out slots: 0 u_emb, 1 pos_emb, 2 neg_emb, 3 u_emb0, 4 pos_emb0, 5 neg_emb0
// *_emb0 slots read fp32 E0 directly — exact.
__global__ void __launch_bounds__(256) k_gather(const int* __restrict__ users,
                                                const int* __restrict__ pos,
                                                const int* __restrict__ neg,
                                                const float* __restrict__ E0,
                                                float* __restrict__ out) {
    int w    = (blockIdx.x * blockDim.x + threadIdx.x) >> 5;
    int lane = threadIdx.x & 31;
    if (w >= 3 * BATCH) return;
    int slot = w / BATCH;
    int b    = w - slot * BATCH;
    int r;
    if (slot == 0)      r = users[b];
    else if (slot == 1) r = N_USERS + pos[b];
    else                r = N_USERS + neg[b];

    // E3 row = (A @ E2)[r] — only needed at gathered rows
    float a0, a1;
    row_gemv_h(g_E2h, r, lane, a0, a1);

    size_t ro = (size_t)r * DIM;
    float  e0a = E0[ro + lane], e0b = E0[ro + lane + 32];
    float2 e1  = __half22float2(g_E1h[(size_t)r * 32 + lane]);
    float2 e2  = __half22float2(g_E2h[(size_t)r * 32 + lane]);
    float f0 = (e0a + e1.x + e2.x + a0) * 0.25f;
    float f1 = (e0b + e1.y + e2.y + a1) * 0.25f;

    size_t base  = (size_t)slot * BATCH * DIM + (size_t)b * DIM;
    size_t base0 = (size_t)(slot + 3) * BATCH * DIM + (size_t)b * DIM;
    out[base  + lane]      = f0;
    out[base  + lane + 32] = f1;
    out[base0 + lane]      = e0a;
    out[base0 + lane + 32] = e0b;
}

// ---------------- launch ----------------

extern "C" void kernel_launch(void* const* d_in, const int* in_sizes, int n_in,
                              void* d_out, int out_size) {
    const int*   users = (const int*)  d_in[0];
    const int*   pos   = (const int*)  d_in[1];
    const int*   neg   = (const int*)  d_in[2];
    const float* E0    = (const float*)d_in[3];
    const int*   arow  = (const int*)  d_in[4];
    const int*   acol  = (const int*)  d_in[5];
    const float* avals = (const float*)d_in[6];
    float* out = (float*)d_out;

    const int e8_blocks   = (NNZ / 8 + 255) / 256;        // 586
    const int spmm_blocks = (N_TOTAL * 32 + 255) / 256;   // 18750

    k_zero<<<(N_TOTAL + 255) / 256, 256>>>();
    k_hist<<<e8_blocks, 256>>>((const int4*)arow);
    k_scan1<<<NBLK_SCAN, SCAN_B>>>();                      // + fused block-sum scan
    k_scatter<<<e8_blocks, 256>>>((const int4*)arow, (const int4*)acol, (const float4*)avals);

    k_spmm1<<<spmm_blocks, 256>>>(E0);                     // 1 warp per row
    k_spmm2<<<spmm_blocks, 256>>>();

    const int gat_blocks = (3 * BATCH * 32 + 255) / 256;
    k_gather<<<gat_blocks, 256>>>(users, pos, neg, E0, out);
}